// round 5
// baseline (speedup 1.0000x reference)
#include <cuda_runtime.h>
#include <cuda_bf16.h>
#include <cstdint>

#define MAX_N 100000
#define MAX_E 1600000
#define HID   64
#define SCAN_TILE 1024
#define MAX_BLKS  ((MAX_N + SCAN_TILE - 1) / SCAN_TILE)

// Scratch: __device__ globals, referenced directly by symbol in device code.
__device__ __align__(16) float g_bufA[MAX_N * HID];
__device__ __align__(16) float g_bufB[MAX_N * HID];
__device__ float g_dis[MAX_N];
__device__ int   g_hist[MAX_N];      // edge in-degree (no self-loop)
__device__ int   g_rowptr[MAX_N];
__device__ int   g_cursor[MAX_N];
__device__ int   g_uhist[MAX_N];     // user_idx counts
__device__ int   g_urowptr[MAX_N];
__device__ int   g_ucursor[MAX_N];
__device__ int   g_unodes[MAX_N];    // CSR payload for user_idx
__device__ int   g_bsums[MAX_BLKS + 1];
__device__ __align__(8) int2 g_erec[MAX_E];  // {src, norm bits}

// ---------------------------------------------------------------------------
__global__ void k_zero_graph(int N) {
    int i = blockIdx.x * blockDim.x + threadIdx.x;
    if (i < N) { g_hist[i] = 0; g_cursor[i] = 0; g_uhist[i] = 0; g_ucursor[i] = 0; }
}

__global__ void k_hist(const int* __restrict__ dst, int E) {
    int e = blockIdx.x * blockDim.x + threadIdx.x;
    if (e < E) atomicAdd(&g_hist[dst[e]], 1);
}

__global__ void k_uhist(const int* __restrict__ uidx, int N) {
    int i = blockIdx.x * blockDim.x + threadIdx.x;
    if (i < N) atomicAdd(&g_uhist[uidx[i]], 1);
}

// dis = (deg+1)^{-1/2}  (self-loop included)
__global__ void k_dis(int N) {
    int i = blockIdx.x * blockDim.x + threadIdx.x;
    if (i < N) g_dis[i] = rsqrtf((float)(g_hist[i] + 1));
}

// ---- hierarchical exclusive scan: which==0 -> hist/rowptr, 1 -> uhist/urowptr
__global__ void __launch_bounds__(SCAN_TILE) k_scan_local(int which, int N) {
    __shared__ int sh[SCAN_TILE];
    const int* in = which ? g_uhist : g_hist;
    int* outp     = which ? g_urowptr : g_rowptr;
    int tid = threadIdx.x;
    int i = blockIdx.x * SCAN_TILE + tid;
    int v = (i < N) ? in[i] : 0;
    sh[tid] = v;
    __syncthreads();
    for (int off = 1; off < SCAN_TILE; off <<= 1) {
        int t = (tid >= off) ? sh[tid - off] : 0;
        __syncthreads();
        sh[tid] += t;
        __syncthreads();
    }
    if (i < N) outp[i] = sh[tid] - v;
    if (tid == SCAN_TILE - 1) g_bsums[blockIdx.x] = sh[tid];
}

__global__ void k_scan_sums(int nblk) {
    if (threadIdx.x == 0 && blockIdx.x == 0) {
        int acc = 0;
        for (int b = 0; b < nblk; ++b) { int t = g_bsums[b]; g_bsums[b] = acc; acc += t; }
    }
}

__global__ void __launch_bounds__(SCAN_TILE) k_scan_add(int which, int N) {
    int* outp = which ? g_urowptr : g_rowptr;
    int i = blockIdx.x * SCAN_TILE + threadIdx.x;
    if (i < N) outp[i] += g_bsums[blockIdx.x];
}

// scatter edges: record {src, dis[src]*dis[dst]} at CSR slot of dst
__global__ void k_scatter(const int* __restrict__ src,
                          const int* __restrict__ dst, int E) {
    int e = blockIdx.x * blockDim.x + threadIdx.x;
    if (e >= E) return;
    int s = src[e];
    int d = dst[e];
    int pos = g_rowptr[d] + atomicAdd(&g_cursor[d], 1);
    g_erec[pos] = make_int2(s, __float_as_int(g_dis[s] * g_dis[d]));
}

__global__ void k_uscatter(const int* __restrict__ uidx, int N) {
    int i = blockIdx.x * blockDim.x + threadIdx.x;
    if (i >= N) return;
    int u = uidx[i];
    int pos = g_urowptr[u] + atomicAdd(&g_ucursor[u], 1);
    g_unodes[pos] = i;
}

// ---------------------------------------------------------------------------
// Gather aggregation: warp per dst node, lanes own cols {lane, lane+32}.
// Reads g_bufA, writes g_bufB:  out = relu?(sum norm*h[src] + dis^2*h[d] + b)
// ---------------------------------------------------------------------------
__global__ void __launch_bounds__(256) k_aggr(const float* __restrict__ bias,
                                              int N, int do_relu) {
    int d = (blockIdx.x * blockDim.x + threadIdx.x) >> 5;
    int lane = threadIdx.x & 31;
    if (d >= N) return;

    float sd = g_dis[d];
    float w = sd * sd;
    int c0 = lane, c1 = lane + 32;
    float a0 = w * g_bufA[(size_t)d * 64 + c0];
    float a1 = w * g_bufA[(size_t)d * 64 + c1];

    int beg = g_rowptr[d];
    int end = beg + g_hist[d];
    for (int e = beg; e < end; ++e) {
        int2 r = g_erec[e];
        int s = r.x;
        float norm = __int_as_float(r.y);
        a0 = fmaf(norm, g_bufA[(size_t)s * 64 + c0], a0);
        a1 = fmaf(norm, g_bufA[(size_t)s * 64 + c1], a1);
    }
    a0 += bias[c0];
    a1 += bias[c1];
    if (do_relu) { a0 = fmaxf(a0, 0.f); a1 = fmaxf(a1, 0.f); }
    g_bufB[(size_t)d * 64 + c0] = a0;
    g_bufB[(size_t)d * 64 + c1] = a1;
}

// ---------------------------------------------------------------------------
// scatter-mean as gather: warp per user u; mean of g_bufB rows listed in CSR.
// Single plain store into d_out. Zero-count users -> 0.
// ---------------------------------------------------------------------------
__global__ void __launch_bounds__(256) k_umean(float* __restrict__ out, int N) {
    int u = (blockIdx.x * blockDim.x + threadIdx.x) >> 5;
    int lane = threadIdx.x & 31;
    if (u >= N) return;
    int c0 = lane, c1 = lane + 32;
    int cnt = g_uhist[u];
    float a0 = 0.f, a1 = 0.f;
    int beg = g_urowptr[u];
    for (int i = beg; i < beg + cnt; ++i) {
        int node = g_unodes[i];
        a0 += g_bufB[(size_t)node * 64 + c0];
        a1 += g_bufB[(size_t)node * 64 + c1];
    }
    float inv = (cnt > 0) ? 1.0f / (float)cnt : 0.f;
    out[(size_t)u * 64 + c0] = a0 * inv;
    out[(size_t)u * 64 + c1] = a1 * inv;
}

// ---------------------------------------------------------------------------
// GEMM: g_bufA[N][64] = A[N][K] @ W[K][64].  in_sel: 0 -> external x, 1 -> g_bufB
// ---------------------------------------------------------------------------
template <int K>
__global__ void __launch_bounds__(256) gemm_kernel(const float* __restrict__ Ax,
                                                   const float* __restrict__ W,
                                                   int in_sel, int N) {
    const float* __restrict__ A = in_sel ? (const float*)g_bufB : Ax;
    __shared__ float Ws[K][64];
    __shared__ float xs[64][33];

    int tid = threadIdx.x;
    for (int i = tid; i < K * 64; i += 256) Ws[i >> 6][i & 63] = W[i];

    int row0 = blockIdx.x * 64;
    int tx = tid & 15;
    int ty = tid >> 4;

    float acc[4][4];
#pragma unroll
    for (int i = 0; i < 4; ++i)
#pragma unroll
        for (int j = 0; j < 4; ++j) acc[i][j] = 0.f;

    for (int k0 = 0; k0 < K; k0 += 32) {
        __syncthreads();
#pragma unroll
        for (int it = 0; it < 2; ++it) {
            int r  = (tid >> 3) + it * 32;
            int kk = (tid & 7) * 4;
            int row = row0 + r;
            float4 v = make_float4(0.f, 0.f, 0.f, 0.f);
            if (row < N)
                v = *(const float4*)(A + (size_t)row * K + k0 + kk);
            xs[r][kk + 0] = v.x; xs[r][kk + 1] = v.y;
            xs[r][kk + 2] = v.z; xs[r][kk + 3] = v.w;
        }
        __syncthreads();
#pragma unroll
        for (int k = 0; k < 32; ++k) {
            float4 bv = *(const float4*)&Ws[k0 + k][tx * 4];
#pragma unroll
            for (int i = 0; i < 4; ++i) {
                float a = xs[ty * 4 + i][k];
                acc[i][0] = fmaf(a, bv.x, acc[i][0]);
                acc[i][1] = fmaf(a, bv.y, acc[i][1]);
                acc[i][2] = fmaf(a, bv.z, acc[i][2]);
                acc[i][3] = fmaf(a, bv.w, acc[i][3]);
            }
        }
    }
#pragma unroll
    for (int i = 0; i < 4; ++i) {
        int row = row0 + ty * 4 + i;
        if (row < N)
            *(float4*)(&g_bufA[(size_t)row * 64 + tx * 4]) =
                make_float4(acc[i][0], acc[i][1], acc[i][2], acc[i][3]);
    }
}

// ---------------------------------------------------------------------------
static inline int cdiv(int a, int b) { return (a + b - 1) / b; }

extern "C" void kernel_launch(void* const* d_in, const int* in_sizes, int n_in,
                              void* d_out, int out_size) {
    const float* x    = (const float*)d_in[0];
    const int*   ei   = (const int*)d_in[1];      // int32 per harness dtype contract
    const int*   uidx = (const int*)d_in[2];
    const float* W1   = (const float*)d_in[3];
    const float* b1   = (const float*)d_in[4];
    const float* W2   = (const float*)d_in[5];
    const float* b2   = (const float*)d_in[6];
    float* out = (float*)d_out;

    const int N = in_sizes[2];
    const int E = in_sizes[1] / 2;
    const int* src = ei;
    const int* dst = ei + E;

    const int TB = 256;
    const int nblk = cdiv(N, SCAN_TILE);

    // ---- build both CSRs (edges by dst; nodes by user_idx) ----
    k_zero_graph<<<cdiv(N, TB), TB>>>(N);
    k_hist<<<cdiv(E, TB), TB>>>(dst, E);
    k_uhist<<<cdiv(N, TB), TB>>>(uidx, N);
    k_dis<<<cdiv(N, TB), TB>>>(N);
    k_scan_local<<<nblk, SCAN_TILE>>>(0, N);
    k_scan_sums<<<1, 32>>>(nblk);
    k_scan_add<<<nblk, SCAN_TILE>>>(0, N);
    k_scan_local<<<nblk, SCAN_TILE>>>(1, N);
    k_scan_sums<<<1, 32>>>(nblk);
    k_scan_add<<<nblk, SCAN_TILE>>>(1, N);
    k_scatter<<<cdiv(E, TB), TB>>>(src, dst, E);
    k_uscatter<<<cdiv(N, TB), TB>>>(uidx, N);

    // ---- Layer 1: gemm (x -> bufA), aggregate (bufA -> bufB, +b1, relu) ----
    gemm_kernel<128><<<cdiv(N, 64), 256>>>(x, W1, 0, N);
    k_aggr<<<cdiv(N * 32, TB), TB>>>(b1, N, 1);

    // ---- Layer 2: gemm (bufB -> bufA), aggregate (bufA -> bufB, +b2) ----
    gemm_kernel<64><<<cdiv(N, 64), 256>>>(x, W2, 1, N);
    k_aggr<<<cdiv(N * 32, TB), TB>>>(b2, N, 0);

    // ---- scatter_mean via gather (bufB -> out), single plain store ----
    k_umean<<<cdiv(N * 32, TB), TB>>>(out, N);
}